// round 11
// baseline (speedup 1.0000x reference)
#include <cuda_runtime.h>
#include <math.h>

// ---------------------------------------------------------------------------
// Problem constants: x (64,128,32,32) -> h (64,256,32,32) -> mixture of ops
// ---------------------------------------------------------------------------
#define BATCH 64
#define CIN_X 128
#define CCH   256
#define HW    32
#define PLANE 1024                 // 32*32
#define NPLANES (BATCH*CCH)        // 16384
#define NTOT (16777216u)           // 64*256*32*32
#define NHW  65536                 // per-channel element count (B*H*W)

// Scratch buffers (device globals: allocation-free, allowed by harness rules)
__device__ float g_h[NTOT];   // activation after input transition (BN+ReLU)
__device__ float g_y[NTOT];   // per-op scratch
__device__ float g_t[NTOT];   // depthwise intermediate for sep_conv
__device__ float g_sel[8];    // thresholded/renormalized mixture weights
__device__ float g_A[CCH];    // per-channel fused BN scale  (sel*g*inv)
__device__ float g_B[CCH];    // per-channel fused BN shift  (sel*(b-m*g*inv))

// ---------------------------------------------------------------------------
// sel computation: softmax -> top-3 -> threshold 0.01 -> renormalize
// ---------------------------------------------------------------------------
__global__ void sel_kernel(const float* __restrict__ aw) {
    if (threadIdx.x != 0) return;
    float w[8];
    float mx = -1e30f;
    for (int i = 0; i < 8; i++) { w[i] = aw[i]; mx = fmaxf(mx, w[i]); }
    float s = 0.f;
    for (int i = 0; i < 8; i++) { w[i] = expf(w[i] - mx); s += w[i]; }
    for (int i = 0; i < 8; i++) w[i] /= s;
    float sel[8]; float tmp[8];
    for (int i = 0; i < 8; i++) { sel[i] = 0.f; tmp[i] = w[i]; }
    for (int t = 0; t < 3; t++) {           // top-3, ties -> lower index (strict >)
        int bi = 0; float bv = tmp[0];
        for (int i = 1; i < 8; i++) if (tmp[i] > bv) { bv = tmp[i]; bi = i; }
        sel[bi] = bv; tmp[bi] = -1e30f;
    }
    float ssum = 0.f;
    for (int i = 0; i < 8; i++) { if (sel[i] < 0.01f) sel[i] = 0.f; ssum += sel[i]; }
    ssum = fmaxf(ssum, 1e-12f);
    for (int i = 0; i < 8; i++) g_sel[i] = sel[i] / ssum;
}

// ---------------------------------------------------------------------------
// Generic implicit-GEMM conv (OIHW weights, NCHW tensors, stride 1)
// Tile: 64 Cout x (4 rows x 32 cols). 256 threads; each thread 8co x 4sp.
// ---------------------------------------------------------------------------
template<int KH, int KW, int DIL, int CI>
__global__ void conv_kernel(const float* __restrict__ in,
                            const float* __restrict__ wgt,
                            float* __restrict__ outp,
                            int Cin, int Cout, int selIdx) {
    if (selIdx >= 0 && g_sel[selIdx] == 0.0f) return;
    constexpr int PAD = DIL * (KH - 1) / 2;
    constexpr int TH  = 4;
    constexpr int IR  = TH + 2 * PAD;
    constexpr int IC  = HW + 2 * PAD;
    constexpr int KK  = KH * KW;

    __shared__ float ws[CI][KK][68];       // 68-pad: avoids 32-way store conflicts
    __shared__ float is[CI][IR][IC];

    const int rt  = blockIdx.x;            // row tile (0..7)
    const int n   = blockIdx.y;            // image
    const int co0 = blockIdx.z * 64;       // cout tile
    const int y0  = rt * TH;

    const int t   = threadIdx.x;
    const int cg  = t & 7;                 // cout group (x8)
    const int sg  = t >> 3;                // spatial group (x4)
    const int y_l = sg >> 3;               // 0..3
    const int x0  = (sg * 4) & 31;

    float acc[8][4];
#pragma unroll
    for (int a = 0; a < 8; a++)
#pragma unroll
        for (int j = 0; j < 4; j++) acc[a][j] = 0.f;

    for (int ci0 = 0; ci0 < Cin; ci0 += CI) {
        __syncthreads();
        // weights: contiguous CI*KK floats per cout row
        for (int idx = t; idx < 64 * CI * KK; idx += 256) {
            int r    = idx % (CI * KK);
            int co_l = idx / (CI * KK);
            int ci   = r / KK;
            int kk   = r % KK;
            ws[ci][kk][co_l] =
                wgt[((size_t)(co0 + co_l) * Cin + ci0) * KK + r];
        }
        // input tile with zero padding
        for (int idx = t; idx < CI * IR * IC; idx += 256) {
            int c  = idx % IC;
            int r  = (idx / IC) % IR;
            int ci = idx / (IC * IR);
            int yy = y0 - PAD + r;
            int xx = c - PAD;
            float v = 0.f;
            if (yy >= 0 && yy < HW && xx >= 0 && xx < HW)
                v = in[(((size_t)n * Cin + ci0 + ci) * HW + yy) * HW + xx];
            is[ci][r][c] = v;
        }
        __syncthreads();

#pragma unroll 1
        for (int ci = 0; ci < CI; ci++) {
#pragma unroll
            for (int ky = 0; ky < KH; ky++) {
#pragma unroll
                for (int kx = 0; kx < KW; kx++) {
                    const float4 w0 = *reinterpret_cast<const float4*>(&ws[ci][ky*KW+kx][cg*8]);
                    const float4 w1 = *reinterpret_cast<const float4*>(&ws[ci][ky*KW+kx][cg*8+4]);
                    const float* ip = &is[ci][y_l + ky*DIL][x0 + kx*DIL];
                    const float i0 = ip[0], i1 = ip[1], i2 = ip[2], i3 = ip[3];
                    const float wv[8] = {w0.x,w0.y,w0.z,w0.w,w1.x,w1.y,w1.z,w1.w};
#pragma unroll
                    for (int a = 0; a < 8; a++) {
                        acc[a][0] += wv[a]*i0;
                        acc[a][1] += wv[a]*i1;
                        acc[a][2] += wv[a]*i2;
                        acc[a][3] += wv[a]*i3;
                    }
                }
            }
        }
    }

#pragma unroll
    for (int a = 0; a < 8; a++) {
        const int co = co0 + cg*8 + a;
        float4 v = make_float4(acc[a][0], acc[a][1], acc[a][2], acc[a][3]);
        *reinterpret_cast<float4*>(
            &outp[(((size_t)n * Cout + co) * HW + y0 + y_l) * HW + x0]) = v;
    }
}

// ---------------------------------------------------------------------------
// Depthwise 3x3 conv (pad 1), one plane per block
// ---------------------------------------------------------------------------
__global__ void dwconv_kernel(const float* __restrict__ in,
                              const float* __restrict__ w,
                              float* __restrict__ outp) {
    if (g_sel[6] == 0.0f) return;
    __shared__ float s[34][34];
    const int plane = blockIdx.x;
    const int c = plane % CCH;
    const float* ip = in + (size_t)plane * PLANE;
    for (int idx = threadIdx.x; idx < 34*34; idx += 256) {
        int r = idx / 34, cc = idx - r*34;
        int yy = r - 1, xx = cc - 1;
        s[r][cc] = (yy >= 0 && yy < 32 && xx >= 0 && xx < 32) ? ip[yy*32 + xx] : 0.f;
    }
    float wv[9];
#pragma unroll
    for (int k = 0; k < 9; k++) wv[k] = w[c*9 + k];
    __syncthreads();
    for (int idx = threadIdx.x; idx < PLANE; idx += 256) {
        int yy = idx >> 5, xx = idx & 31;
        float a = 0.f;
#pragma unroll
        for (int ky = 0; ky < 3; ky++)
#pragma unroll
            for (int kx = 0; kx < 3; kx++)
                a += s[yy+ky][xx+kx] * wv[ky*3+kx];
        outp[(size_t)plane * PLANE + idx] = a;
    }
}

// ---------------------------------------------------------------------------
// 3x3 max pool (pad 1) and 3x3 avg pool (count_include_pad), per-plane blocks
// ---------------------------------------------------------------------------
__global__ void maxpool_kernel(const float* __restrict__ in, float* __restrict__ outp) {
    if (g_sel[1] == 0.0f) return;
    __shared__ float s[34][34];
    const int plane = blockIdx.x;
    const float* ip = in + (size_t)plane * PLANE;
    for (int idx = threadIdx.x; idx < 34*34; idx += 256) {
        int r = idx / 34, cc = idx - r*34;
        int yy = r - 1, xx = cc - 1;
        s[r][cc] = (yy >= 0 && yy < 32 && xx >= 0 && xx < 32) ? ip[yy*32 + xx] : -3.0e38f;
    }
    __syncthreads();
    for (int idx = threadIdx.x; idx < PLANE; idx += 256) {
        int yy = idx >> 5, xx = idx & 31;
        float m = -3.0e38f;
#pragma unroll
        for (int ky = 0; ky < 3; ky++)
#pragma unroll
            for (int kx = 0; kx < 3; kx++)
                m = fmaxf(m, s[yy+ky][xx+kx]);
        outp[(size_t)plane * PLANE + idx] = m;
    }
}

__global__ void avgpool_kernel(const float* __restrict__ in, float* __restrict__ outp) {
    if (g_sel[2] == 0.0f) return;
    __shared__ float s[34][34];
    const int plane = blockIdx.x;
    const float* ip = in + (size_t)plane * PLANE;
    for (int idx = threadIdx.x; idx < 34*34; idx += 256) {
        int r = idx / 34, cc = idx - r*34;
        int yy = r - 1, xx = cc - 1;
        s[r][cc] = (yy >= 0 && yy < 32 && xx >= 0 && xx < 32) ? ip[yy*32 + xx] : 0.f;
    }
    __syncthreads();
    const float inv9 = 1.0f / 9.0f;
    for (int idx = threadIdx.x; idx < PLANE; idx += 256) {
        int yy = idx >> 5, xx = idx & 31;
        float a = 0.f;
#pragma unroll
        for (int ky = 0; ky < 3; ky++)
#pragma unroll
            for (int kx = 0; kx < 3; kx++)
                a += s[yy+ky][xx+kx];
        outp[(size_t)plane * PLANE + idx] = a * inv9;
    }
}

// ---------------------------------------------------------------------------
// Per-channel mean/var -> fused BN scale/shift (with sel folded in)
// One block per channel, deterministic tree reduction.
// ---------------------------------------------------------------------------
__global__ void stats_kernel(const float* __restrict__ y,
                             const float* __restrict__ g,
                             const float* __restrict__ b,
                             int selIdx) {
    const float sel = (selIdx >= 0) ? g_sel[selIdx] : 1.0f;
    if (sel == 0.0f) return;
    const int c = blockIdx.x;
    const float* base = y + (size_t)c * PLANE;
    float s = 0.f, s2 = 0.f;
    for (int idx = threadIdx.x; idx < NHW; idx += 256) {
        int n = idx >> 10, i = idx & 1023;
        float v = base[(size_t)n * (CCH * PLANE) + i];
        s += v; s2 += v * v;
    }
    __shared__ float rs[256], rs2[256];
    rs[threadIdx.x] = s; rs2[threadIdx.x] = s2;
    __syncthreads();
    for (int o = 128; o > 0; o >>= 1) {
        if (threadIdx.x < o) { rs[threadIdx.x] += rs[threadIdx.x+o]; rs2[threadIdx.x] += rs2[threadIdx.x+o]; }
        __syncthreads();
    }
    if (threadIdx.x == 0) {
        float m   = rs[0] * (1.0f / (float)NHW);
        float var = rs2[0] * (1.0f / (float)NHW) - m * m;
        float inv = rsqrtf(var + 1e-5f);
        float A   = g[c] * inv;
        g_A[c] = sel * A;
        g_B[c] = sel * (b[c] - m * A);
    }
}

// ---------------------------------------------------------------------------
// Elementwise kernels (float4, channel derived from linear index)
// ---------------------------------------------------------------------------
__global__ void norm_relu_kernel(float* __restrict__ h) {
    size_t i4 = (size_t)blockIdx.x * 256 + threadIdx.x;
    int c = (int)((i4 >> 8) & 255);
    float A = g_A[c], Bv = g_B[c];
    float4 v = reinterpret_cast<float4*>(h)[i4];
    v.x = fmaxf(v.x * A + Bv, 0.f);
    v.y = fmaxf(v.y * A + Bv, 0.f);
    v.z = fmaxf(v.z * A + Bv, 0.f);
    v.w = fmaxf(v.w * A + Bv, 0.f);
    reinterpret_cast<float4*>(h)[i4] = v;
}

__global__ void init_out_kernel(float* __restrict__ out, const float* __restrict__ h) {
    size_t i4 = (size_t)blockIdx.x * 256 + threadIdx.x;
    float s = g_sel[3];
    float4 v = reinterpret_cast<const float4*>(h)[i4];
    v.x *= s; v.y *= s; v.z *= s; v.w *= s;
    reinterpret_cast<float4*>(out)[i4] = v;
}

__global__ void accum_kernel(float* __restrict__ out, const float* __restrict__ y, int selIdx) {
    if (g_sel[selIdx] == 0.0f) return;
    size_t i4 = (size_t)blockIdx.x * 256 + threadIdx.x;
    int c = (int)((i4 >> 8) & 255);
    float A = g_A[c], Bv = g_B[c];
    float4 v = reinterpret_cast<const float4*>(y)[i4];
    float4 o = reinterpret_cast<float4*>(out)[i4];
    o.x += v.x * A + Bv;
    o.y += v.y * A + Bv;
    o.z += v.z * A + Bv;
    o.w += v.w * A + Bv;
    reinterpret_cast<float4*>(out)[i4] = o;
}

// ---------------------------------------------------------------------------
// Launch sequence (graph-capturable, allocation-free)
// ---------------------------------------------------------------------------
extern "C" void kernel_launch(void* const* d_in, const int* in_sizes, int n_in,
                              void* d_out, int out_size) {
    const float* x    = (const float*)d_in[0];
    const float* aw   = (const float*)d_in[1];
    const float* w_in = (const float*)d_in[2];
    const float* g_in = (const float*)d_in[3];
    const float* b_in = (const float*)d_in[4];
    const float* w3   = (const float*)d_in[5];
    const float* g3   = (const float*)d_in[6];
    const float* b3   = (const float*)d_in[7];
    const float* w5   = (const float*)d_in[8];
    const float* g5   = (const float*)d_in[9];
    const float* b5   = (const float*)d_in[10];
    const float* w_dw = (const float*)d_in[11];
    const float* w_pw = (const float*)d_in[12];
    const float* gs   = (const float*)d_in[13];
    const float* bs   = (const float*)d_in[14];
    const float* wd   = (const float*)d_in[15];
    const float* gd   = (const float*)d_in[16];
    const float* bd   = (const float*)d_in[17];
    const float* gmp  = (const float*)d_in[18];
    const float* bmp  = (const float*)d_in[19];
    const float* gap  = (const float*)d_in[20];
    const float* bap  = (const float*)d_in[21];
    float* out = (float*)d_out;

    float *h, *y, *t;
    cudaGetSymbolAddress((void**)&h, g_h);
    cudaGetSymbolAddress((void**)&y, g_y);
    cudaGetSymbolAddress((void**)&t, g_t);

    const dim3 convGrid(8, BATCH, CCH / 64);
    const int  eltGrid = NTOT / 4 / 256;   // 16384

    // mixture weights
    sel_kernel<<<1, 32>>>(aw);

    // input transition: conv1x1 -> BN -> ReLU (h)
    conv_kernel<1,1,1,16><<<convGrid, 256>>>(x, w_in, h, CIN_X, CCH, -1);
    stats_kernel<<<CCH, 256>>>(h, g_in, b_in, -1);
    norm_relu_kernel<<<eltGrid, 256>>>(h);

    // out = sel[3] * h (also clears poison)
    init_out_kernel<<<eltGrid, 256>>>(out, h);

    // op 1: max_pool_3x3
    maxpool_kernel<<<NPLANES, 256>>>(h, y);
    stats_kernel<<<CCH, 256>>>(y, gmp, bmp, 1);
    accum_kernel<<<eltGrid, 256>>>(out, y, 1);

    // op 2: avg_pool_3x3
    avgpool_kernel<<<NPLANES, 256>>>(h, y);
    stats_kernel<<<CCH, 256>>>(y, gap, bap, 2);
    accum_kernel<<<eltGrid, 256>>>(out, y, 2);

    // op 4: conv_3x3
    conv_kernel<3,3,1,8><<<convGrid, 256>>>(h, w3, y, CCH, CCH, 4);
    stats_kernel<<<CCH, 256>>>(y, g3, b3, 4);
    accum_kernel<<<eltGrid, 256>>>(out, y, 4);

    // op 5: conv_5x5
    conv_kernel<5,5,1,4><<<convGrid, 256>>>(h, w5, y, CCH, CCH, 5);
    stats_kernel<<<CCH, 256>>>(y, g5, b5, 5);
    accum_kernel<<<eltGrid, 256>>>(out, y, 5);

    // op 6: sep_conv_3x3 (depthwise 3x3 -> pointwise 1x1)
    dwconv_kernel<<<NPLANES, 256>>>(h, w_dw, t);
    conv_kernel<1,1,1,16><<<convGrid, 256>>>(t, w_pw, y, CCH, CCH, 6);
    stats_kernel<<<CCH, 256>>>(y, gs, bs, 6);
    accum_kernel<<<eltGrid, 256>>>(out, y, 6);

    // op 7: dil_conv_3x3 (dilation 2, pad 2)
    conv_kernel<3,3,2,8><<<convGrid, 256>>>(h, wd, y, CCH, CCH, 7);
    stats_kernel<<<CCH, 256>>>(y, gd, bd, 7);
    accum_kernel<<<eltGrid, 256>>>(out, y, 7);
}

// round 12
// speedup vs baseline: 1.0012x; 1.0012x over previous
#include <cuda_runtime.h>
#include <math.h>

// ---------------------------------------------------------------------------
// Problem constants: x (64,128,32,32) -> h (64,256,32,32) -> mixture of ops
// ---------------------------------------------------------------------------
#define BATCH 64
#define CIN_X 128
#define CCH   256
#define HW    32
#define PLANE 1024                 // 32*32
#define NPLANES (BATCH*CCH)        // 16384
#define NTOT (16777216u)           // 64*256*32*32
#define NHW  65536                 // per-channel element count (B*H*W)

// Scratch buffers (device globals: allocation-free, allowed by harness rules)
__device__ float g_h[NTOT];   // activation after input transition (BN+ReLU)
__device__ float g_y[NTOT];   // per-op scratch
__device__ float g_t[NTOT];   // depthwise intermediate for sep_conv
__device__ float g_sel[8];    // thresholded/renormalized mixture weights
__device__ float g_A[CCH];    // per-channel fused BN scale  (sel*g*inv)
__device__ float g_B[CCH];    // per-channel fused BN shift  (sel*(b-m*g*inv))

// ---------------------------------------------------------------------------
// sel computation: softmax -> top-3 -> threshold 0.01 -> renormalize
// ---------------------------------------------------------------------------
__global__ void sel_kernel(const float* __restrict__ aw) {
    if (threadIdx.x != 0) return;
    float w[8];
    float mx = -1e30f;
    for (int i = 0; i < 8; i++) { w[i] = aw[i]; mx = fmaxf(mx, w[i]); }
    float s = 0.f;
    for (int i = 0; i < 8; i++) { w[i] = expf(w[i] - mx); s += w[i]; }
    for (int i = 0; i < 8; i++) w[i] /= s;
    float sel[8]; float tmp[8];
    for (int i = 0; i < 8; i++) { sel[i] = 0.f; tmp[i] = w[i]; }
    for (int t = 0; t < 3; t++) {           // top-3, ties -> lower index (strict >)
        int bi = 0; float bv = tmp[0];
        for (int i = 1; i < 8; i++) if (tmp[i] > bv) { bv = tmp[i]; bi = i; }
        sel[bi] = bv; tmp[bi] = -1e30f;
    }
    float ssum = 0.f;
    for (int i = 0; i < 8; i++) { if (sel[i] < 0.01f) sel[i] = 0.f; ssum += sel[i]; }
    ssum = fmaxf(ssum, 1e-12f);
    for (int i = 0; i < 8; i++) g_sel[i] = sel[i] / ssum;
}

// ---------------------------------------------------------------------------
// Generic implicit-GEMM conv (OIHW weights, NCHW tensors, stride 1)
// Tile: 64 Cout x (4 rows x 32 cols). 256 threads; each thread 8co x 4sp.
// ---------------------------------------------------------------------------
template<int KH, int KW, int DIL, int CI>
__global__ void conv_kernel(const float* __restrict__ in,
                            const float* __restrict__ wgt,
                            float* __restrict__ outp,
                            int Cin, int Cout, int selIdx) {
    if (selIdx >= 0 && g_sel[selIdx] == 0.0f) return;
    constexpr int PAD = DIL * (KH - 1) / 2;
    constexpr int TH  = 4;
    constexpr int IR  = TH + 2 * PAD;
    constexpr int IC  = HW + 2 * PAD;
    constexpr int KK  = KH * KW;

    __shared__ float ws[CI][KK][68];       // 68-pad: avoids 32-way store conflicts
    __shared__ float is[CI][IR][IC];

    const int rt  = blockIdx.x;            // row tile (0..7)
    const int n   = blockIdx.y;            // image
    const int co0 = blockIdx.z * 64;       // cout tile
    const int y0  = rt * TH;

    const int t   = threadIdx.x;
    const int cg  = t & 7;                 // cout group (x8)
    const int sg  = t >> 3;                // spatial group (x4)
    const int y_l = sg >> 3;               // 0..3
    const int x0  = (sg * 4) & 31;

    float acc[8][4];
#pragma unroll
    for (int a = 0; a < 8; a++)
#pragma unroll
        for (int j = 0; j < 4; j++) acc[a][j] = 0.f;

    for (int ci0 = 0; ci0 < Cin; ci0 += CI) {
        __syncthreads();
        // weights: contiguous CI*KK floats per cout row
        for (int idx = t; idx < 64 * CI * KK; idx += 256) {
            int r    = idx % (CI * KK);
            int co_l = idx / (CI * KK);
            int ci   = r / KK;
            int kk   = r % KK;
            ws[ci][kk][co_l] =
                wgt[((size_t)(co0 + co_l) * Cin + ci0) * KK + r];
        }
        // input tile with zero padding
        for (int idx = t; idx < CI * IR * IC; idx += 256) {
            int c  = idx % IC;
            int r  = (idx / IC) % IR;
            int ci = idx / (IC * IR);
            int yy = y0 - PAD + r;
            int xx = c - PAD;
            float v = 0.f;
            if (yy >= 0 && yy < HW && xx >= 0 && xx < HW)
                v = in[(((size_t)n * Cin + ci0 + ci) * HW + yy) * HW + xx];
            is[ci][r][c] = v;
        }
        __syncthreads();

#pragma unroll 1
        for (int ci = 0; ci < CI; ci++) {
#pragma unroll
            for (int ky = 0; ky < KH; ky++) {
#pragma unroll
                for (int kx = 0; kx < KW; kx++) {
                    const float4 w0 = *reinterpret_cast<const float4*>(&ws[ci][ky*KW+kx][cg*8]);
                    const float4 w1 = *reinterpret_cast<const float4*>(&ws[ci][ky*KW+kx][cg*8+4]);
                    const float* ip = &is[ci][y_l + ky*DIL][x0 + kx*DIL];
                    const float i0 = ip[0], i1 = ip[1], i2 = ip[2], i3 = ip[3];
                    const float wv[8] = {w0.x,w0.y,w0.z,w0.w,w1.x,w1.y,w1.z,w1.w};
#pragma unroll
                    for (int a = 0; a < 8; a++) {
                        acc[a][0] += wv[a]*i0;
                        acc[a][1] += wv[a]*i1;
                        acc[a][2] += wv[a]*i2;
                        acc[a][3] += wv[a]*i3;
                    }
                }
            }
        }
    }

#pragma unroll
    for (int a = 0; a < 8; a++) {
        const int co = co0 + cg*8 + a;
        float4 v = make_float4(acc[a][0], acc[a][1], acc[a][2], acc[a][3]);
        *reinterpret_cast<float4*>(
            &outp[(((size_t)n * Cout + co) * HW + y0 + y_l) * HW + x0]) = v;
    }
}

// ---------------------------------------------------------------------------
// Depthwise 3x3 conv (pad 1), one plane per block
// ---------------------------------------------------------------------------
__global__ void dwconv_kernel(const float* __restrict__ in,
                              const float* __restrict__ w,
                              float* __restrict__ outp) {
    if (g_sel[6] == 0.0f) return;
    __shared__ float s[34][34];
    const int plane = blockIdx.x;
    const int c = plane % CCH;
    const float* ip = in + (size_t)plane * PLANE;
    for (int idx = threadIdx.x; idx < 34*34; idx += 256) {
        int r = idx / 34, cc = idx - r*34;
        int yy = r - 1, xx = cc - 1;
        s[r][cc] = (yy >= 0 && yy < 32 && xx >= 0 && xx < 32) ? ip[yy*32 + xx] : 0.f;
    }
    float wv[9];
#pragma unroll
    for (int k = 0; k < 9; k++) wv[k] = w[c*9 + k];
    __syncthreads();
    for (int idx = threadIdx.x; idx < PLANE; idx += 256) {
        int yy = idx >> 5, xx = idx & 31;
        float a = 0.f;
#pragma unroll
        for (int ky = 0; ky < 3; ky++)
#pragma unroll
            for (int kx = 0; kx < 3; kx++)
                a += s[yy+ky][xx+kx] * wv[ky*3+kx];
        outp[(size_t)plane * PLANE + idx] = a;
    }
}

// ---------------------------------------------------------------------------
// 3x3 max pool (pad 1) and 3x3 avg pool (count_include_pad), per-plane blocks
// ---------------------------------------------------------------------------
__global__ void maxpool_kernel(const float* __restrict__ in, float* __restrict__ outp) {
    if (g_sel[1] == 0.0f) return;
    __shared__ float s[34][34];
    const int plane = blockIdx.x;
    const float* ip = in + (size_t)plane * PLANE;
    for (int idx = threadIdx.x; idx < 34*34; idx += 256) {
        int r = idx / 34, cc = idx - r*34;
        int yy = r - 1, xx = cc - 1;
        s[r][cc] = (yy >= 0 && yy < 32 && xx >= 0 && xx < 32) ? ip[yy*32 + xx] : -3.0e38f;
    }
    __syncthreads();
    for (int idx = threadIdx.x; idx < PLANE; idx += 256) {
        int yy = idx >> 5, xx = idx & 31;
        float m = -3.0e38f;
#pragma unroll
        for (int ky = 0; ky < 3; ky++)
#pragma unroll
            for (int kx = 0; kx < 3; kx++)
                m = fmaxf(m, s[yy+ky][xx+kx]);
        outp[(size_t)plane * PLANE + idx] = m;
    }
}

__global__ void avgpool_kernel(const float* __restrict__ in, float* __restrict__ outp) {
    if (g_sel[2] == 0.0f) return;
    __shared__ float s[34][34];
    const int plane = blockIdx.x;
    const float* ip = in + (size_t)plane * PLANE;
    for (int idx = threadIdx.x; idx < 34*34; idx += 256) {
        int r = idx / 34, cc = idx - r*34;
        int yy = r - 1, xx = cc - 1;
        s[r][cc] = (yy >= 0 && yy < 32 && xx >= 0 && xx < 32) ? ip[yy*32 + xx] : 0.f;
    }
    __syncthreads();
    const float inv9 = 1.0f / 9.0f;
    for (int idx = threadIdx.x; idx < PLANE; idx += 256) {
        int yy = idx >> 5, xx = idx & 31;
        float a = 0.f;
#pragma unroll
        for (int ky = 0; ky < 3; ky++)
#pragma unroll
            for (int kx = 0; kx < 3; kx++)
                a += s[yy+ky][xx+kx];
        outp[(size_t)plane * PLANE + idx] = a * inv9;
    }
}

// ---------------------------------------------------------------------------
// Per-channel mean/var -> fused BN scale/shift (with sel folded in)
// One block per channel, deterministic tree reduction.
// ---------------------------------------------------------------------------
__global__ void stats_kernel(const float* __restrict__ y,
                             const float* __restrict__ g,
                             const float* __restrict__ b,
                             int selIdx) {
    const float sel = (selIdx >= 0) ? g_sel[selIdx] : 1.0f;
    if (sel == 0.0f) return;
    const int c = blockIdx.x;
    const float* base = y + (size_t)c * PLANE;
    float s = 0.f, s2 = 0.f;
    for (int idx = threadIdx.x; idx < NHW; idx += 256) {
        int n = idx >> 10, i = idx & 1023;
        float v = base[(size_t)n * (CCH * PLANE) + i];
        s += v; s2 += v * v;
    }
    __shared__ float rs[256], rs2[256];
    rs[threadIdx.x] = s; rs2[threadIdx.x] = s2;
    __syncthreads();
    for (int o = 128; o > 0; o >>= 1) {
        if (threadIdx.x < o) { rs[threadIdx.x] += rs[threadIdx.x+o]; rs2[threadIdx.x] += rs2[threadIdx.x+o]; }
        __syncthreads();
    }
    if (threadIdx.x == 0) {
        float m   = rs[0] * (1.0f / (float)NHW);
        float var = rs2[0] * (1.0f / (float)NHW) - m * m;
        float inv = rsqrtf(var + 1e-5f);
        float A   = g[c] * inv;
        g_A[c] = sel * A;
        g_B[c] = sel * (b[c] - m * A);
    }
}

// ---------------------------------------------------------------------------
// Elementwise kernels (float4, channel derived from linear index)
// ---------------------------------------------------------------------------
__global__ void norm_relu_kernel(float* __restrict__ h) {
    size_t i4 = (size_t)blockIdx.x * 256 + threadIdx.x;
    int c = (int)((i4 >> 8) & 255);
    float A = g_A[c], Bv = g_B[c];
    float4 v = reinterpret_cast<float4*>(h)[i4];
    v.x = fmaxf(v.x * A + Bv, 0.f);
    v.y = fmaxf(v.y * A + Bv, 0.f);
    v.z = fmaxf(v.z * A + Bv, 0.f);
    v.w = fmaxf(v.w * A + Bv, 0.f);
    reinterpret_cast<float4*>(h)[i4] = v;
}

__global__ void init_out_kernel(float* __restrict__ out, const float* __restrict__ h) {
    size_t i4 = (size_t)blockIdx.x * 256 + threadIdx.x;
    float s = g_sel[3];
    float4 v = reinterpret_cast<const float4*>(h)[i4];
    v.x *= s; v.y *= s; v.z *= s; v.w *= s;
    reinterpret_cast<float4*>(out)[i4] = v;
}

__global__ void accum_kernel(float* __restrict__ out, const float* __restrict__ y, int selIdx) {
    if (g_sel[selIdx] == 0.0f) return;
    size_t i4 = (size_t)blockIdx.x * 256 + threadIdx.x;
    int c = (int)((i4 >> 8) & 255);
    float A = g_A[c], Bv = g_B[c];
    float4 v = reinterpret_cast<const float4*>(y)[i4];
    float4 o = reinterpret_cast<float4*>(out)[i4];
    o.x += v.x * A + Bv;
    o.y += v.y * A + Bv;
    o.z += v.z * A + Bv;
    o.w += v.w * A + Bv;
    reinterpret_cast<float4*>(out)[i4] = o;
}

// ---------------------------------------------------------------------------
// Launch sequence (graph-capturable, allocation-free)
// ---------------------------------------------------------------------------
extern "C" void kernel_launch(void* const* d_in, const int* in_sizes, int n_in,
                              void* d_out, int out_size) {
    const float* x    = (const float*)d_in[0];
    const float* aw   = (const float*)d_in[1];
    const float* w_in = (const float*)d_in[2];
    const float* g_in = (const float*)d_in[3];
    const float* b_in = (const float*)d_in[4];
    const float* w3   = (const float*)d_in[5];
    const float* g3   = (const float*)d_in[6];
    const float* b3   = (const float*)d_in[7];
    const float* w5   = (const float*)d_in[8];
    const float* g5   = (const float*)d_in[9];
    const float* b5   = (const float*)d_in[10];
    const float* w_dw = (const float*)d_in[11];
    const float* w_pw = (const float*)d_in[12];
    const float* gs   = (const float*)d_in[13];
    const float* bs   = (const float*)d_in[14];
    const float* wd   = (const float*)d_in[15];
    const float* gd   = (const float*)d_in[16];
    const float* bd   = (const float*)d_in[17];
    const float* gmp  = (const float*)d_in[18];
    const float* bmp  = (const float*)d_in[19];
    const float* gap  = (const float*)d_in[20];
    const float* bap  = (const float*)d_in[21];
    float* out = (float*)d_out;

    float *h, *y, *t;
    cudaGetSymbolAddress((void**)&h, g_h);
    cudaGetSymbolAddress((void**)&y, g_y);
    cudaGetSymbolAddress((void**)&t, g_t);

    const dim3 convGrid(8, BATCH, CCH / 64);
    const int  eltGrid = NTOT / 4 / 256;   // 16384

    // mixture weights
    sel_kernel<<<1, 32>>>(aw);

    // input transition: conv1x1 -> BN -> ReLU (h)
    conv_kernel<1,1,1,16><<<convGrid, 256>>>(x, w_in, h, CIN_X, CCH, -1);
    stats_kernel<<<CCH, 256>>>(h, g_in, b_in, -1);
    norm_relu_kernel<<<eltGrid, 256>>>(h);

    // out = sel[3] * h (also clears poison)
    init_out_kernel<<<eltGrid, 256>>>(out, h);

    // op 1: max_pool_3x3
    maxpool_kernel<<<NPLANES, 256>>>(h, y);
    stats_kernel<<<CCH, 256>>>(y, gmp, bmp, 1);
    accum_kernel<<<eltGrid, 256>>>(out, y, 1);

    // op 2: avg_pool_3x3
    avgpool_kernel<<<NPLANES, 256>>>(h, y);
    stats_kernel<<<CCH, 256>>>(y, gap, bap, 2);
    accum_kernel<<<eltGrid, 256>>>(out, y, 2);

    // op 4: conv_3x3
    conv_kernel<3,3,1,8><<<convGrid, 256>>>(h, w3, y, CCH, CCH, 4);
    stats_kernel<<<CCH, 256>>>(y, g3, b3, 4);
    accum_kernel<<<eltGrid, 256>>>(out, y, 4);

    // op 5: conv_5x5
    conv_kernel<5,5,1,4><<<convGrid, 256>>>(h, w5, y, CCH, CCH, 5);
    stats_kernel<<<CCH, 256>>>(y, g5, b5, 5);
    accum_kernel<<<eltGrid, 256>>>(out, y, 5);

    // op 6: sep_conv_3x3 (depthwise 3x3 -> pointwise 1x1)
    dwconv_kernel<<<NPLANES, 256>>>(h, w_dw, t);
    conv_kernel<1,1,1,16><<<convGrid, 256>>>(t, w_pw, y, CCH, CCH, 6);
    stats_kernel<<<CCH, 256>>>(y, gs, bs, 6);
    accum_kernel<<<eltGrid, 256>>>(out, y, 6);

    // op 7: dil_conv_3x3 (dilation 2, pad 2)
    conv_kernel<3,3,2,8><<<convGrid, 256>>>(h, wd, y, CCH, CCH, 7);
    stats_kernel<<<CCH, 256>>>(y, gd, bd, 7);
    accum_kernel<<<eltGrid, 256>>>(out, y, 7);
}

// round 13
// speedup vs baseline: 1.0544x; 1.0532x over previous
#include <cuda_runtime.h>
#include <math.h>
#include <stdint.h>

// ---------------------------------------------------------------------------
// Problem constants: x (64,128,32,32) -> h (64,256,32,32) -> mixture of ops
// ---------------------------------------------------------------------------
#define BATCH 64
#define CIN_X 128
#define CCH   256
#define HW    32
#define PLANE 1024                 // 32*32
#define NPLANES (BATCH*CCH)        // 16384
#define NTOT (16777216u)           // 64*256*32*32
#define NHW  65536                 // per-channel element count (B*H*W)

typedef unsigned long long u64;

// Packed fp32x2 FMA (Blackwell sm_100+): d = a*b + d on two packed fp32 lanes.
__device__ __forceinline__ void ffma2(u64& d, u64 a, u64 b) {
    asm("fma.rn.f32x2 %0, %1, %2, %0;" : "+l"(d) : "l"(a), "l"(b));
}
__device__ __forceinline__ u64 bcast2(float v) {
    u64 r; uint32_t iv = __float_as_uint(v);
    asm("mov.b64 %0, {%1, %1};" : "=l"(r) : "r"(iv));
    return r;
}
__device__ __forceinline__ void unpack2(u64 p, float& lo, float& hi) {
    asm("mov.b64 {%0, %1}, %2;" : "=f"(lo), "=f"(hi) : "l"(p));
}

// Scratch buffers (device globals: allocation-free)
__device__ float g_h[NTOT];   // activation after input transition (BN+ReLU)
__device__ float g_y[NTOT];   // per-op scratch
__device__ float g_t[NTOT];   // depthwise intermediate for sep_conv
__device__ float g_sel[8];    // thresholded/renormalized mixture weights
__device__ float g_A[CCH];    // per-channel fused BN scale
__device__ float g_B[CCH];    // per-channel fused BN shift

// ---------------------------------------------------------------------------
// sel computation: softmax -> top-3 -> threshold 0.01 -> renormalize
// ---------------------------------------------------------------------------
__global__ void sel_kernel(const float* __restrict__ aw) {
    if (threadIdx.x != 0) return;
    float w[8];
    float mx = -1e30f;
    for (int i = 0; i < 8; i++) { w[i] = aw[i]; mx = fmaxf(mx, w[i]); }
    float s = 0.f;
    for (int i = 0; i < 8; i++) { w[i] = expf(w[i] - mx); s += w[i]; }
    for (int i = 0; i < 8; i++) w[i] /= s;
    float sel[8]; float tmp[8];
    for (int i = 0; i < 8; i++) { sel[i] = 0.f; tmp[i] = w[i]; }
    for (int t = 0; t < 3; t++) {
        int bi = 0; float bv = tmp[0];
        for (int i = 1; i < 8; i++) if (tmp[i] > bv) { bv = tmp[i]; bi = i; }
        sel[bi] = bv; tmp[bi] = -1e30f;
    }
    float ssum = 0.f;
    for (int i = 0; i < 8; i++) { if (sel[i] < 0.01f) sel[i] = 0.f; ssum += sel[i]; }
    ssum = fmaxf(ssum, 1e-12f);
    for (int i = 0; i < 8; i++) g_sel[i] = sel[i] / ssum;
}

// ---------------------------------------------------------------------------
// Implicit-GEMM conv with packed f32x2 FMAs.
// Tile: 64 Cout x (4 rows x 32 cols). 256 threads; each thread 4 cout-pairs x 4sp.
// ---------------------------------------------------------------------------
template<int KH, int KW, int DIL, int CI>
__global__ void conv_kernel(const float* __restrict__ in,
                            const float* __restrict__ wgt,
                            float* __restrict__ outp,
                            int Cin, int Cout, int selIdx) {
    if (selIdx >= 0 && g_sel[selIdx] == 0.0f) return;
    constexpr int PAD = DIL * (KH - 1) / 2;
    constexpr int TH  = 4;
    constexpr int IR  = TH + 2 * PAD;
    constexpr int IC  = HW + 2 * PAD;
    constexpr int KK  = KH * KW;

    __shared__ __align__(16) float ws[CI][KK][68];   // 68-pad vs conflicts; rows 16B-mult
    __shared__ __align__(16) float is[CI][IR][IC];

    const int rt  = blockIdx.x;            // row tile (0..7)
    const int n   = blockIdx.y;            // image
    const int co0 = blockIdx.z * 64;       // cout tile
    const int y0  = rt * TH;

    const int t   = threadIdx.x;
    const int cg  = t & 7;                 // cout group (x8)
    const int sg  = t >> 3;                // spatial group (x4)
    const int y_l = sg >> 3;               // 0..3
    const int x0  = (sg * 4) & 31;

    u64 acc2[4][4];                        // [cout-pair][spatial], packed {lo,hi}
#pragma unroll
    for (int a = 0; a < 4; a++)
#pragma unroll
        for (int j = 0; j < 4; j++) acc2[a][j] = 0ULL;

    for (int ci0 = 0; ci0 < Cin; ci0 += CI) {
        __syncthreads();
        // weights: contiguous CI*KK floats per cout row
        for (int idx = t; idx < 64 * CI * KK; idx += 256) {
            int r    = idx % (CI * KK);
            int co_l = idx / (CI * KK);
            int ci   = r / KK;
            int kk   = r % KK;
            ws[ci][kk][co_l] =
                wgt[((size_t)(co0 + co_l) * Cin + ci0) * KK + r];
        }
        // input tile with zero padding
        for (int idx = t; idx < CI * IR * IC; idx += 256) {
            int c  = idx % IC;
            int r  = (idx / IC) % IR;
            int ci = idx / (IC * IR);
            int yy = y0 - PAD + r;
            int xx = c - PAD;
            float v = 0.f;
            if (yy >= 0 && yy < HW && xx >= 0 && xx < HW)
                v = in[(((size_t)n * Cin + ci0 + ci) * HW + yy) * HW + xx];
            is[ci][r][c] = v;
        }
        __syncthreads();

#pragma unroll 1
        for (int ci = 0; ci < CI; ci++) {
#pragma unroll
            for (int ky = 0; ky < KH; ky++) {
#pragma unroll
                for (int kx = 0; kx < KW; kx++) {
                    // 8 consecutive couts = 4 aligned 64-bit pairs in smem
                    const u64* wp = reinterpret_cast<const u64*>(&ws[ci][ky*KW+kx][cg*8]);
                    const u64 w0 = wp[0], w1 = wp[1], w2 = wp[2], w3 = wp[3];
                    const float* ip = &is[ci][y_l + ky*DIL][x0 + kx*DIL];
                    const u64 b0 = bcast2(ip[0]);
                    const u64 b1 = bcast2(ip[1]);
                    const u64 b2 = bcast2(ip[2]);
                    const u64 b3 = bcast2(ip[3]);
                    ffma2(acc2[0][0], w0, b0); ffma2(acc2[0][1], w0, b1);
                    ffma2(acc2[0][2], w0, b2); ffma2(acc2[0][3], w0, b3);
                    ffma2(acc2[1][0], w1, b0); ffma2(acc2[1][1], w1, b1);
                    ffma2(acc2[1][2], w1, b2); ffma2(acc2[1][3], w1, b3);
                    ffma2(acc2[2][0], w2, b0); ffma2(acc2[2][1], w2, b1);
                    ffma2(acc2[2][2], w2, b2); ffma2(acc2[2][3], w2, b3);
                    ffma2(acc2[3][0], w3, b0); ffma2(acc2[3][1], w3, b1);
                    ffma2(acc2[3][2], w3, b2); ffma2(acc2[3][3], w3, b3);
                }
            }
        }
    }

    // unpack into per-cout rows and store float4 per row
    float accf[8][4];
#pragma unroll
    for (int a = 0; a < 4; a++)
#pragma unroll
        for (int j = 0; j < 4; j++)
            unpack2(acc2[a][j], accf[2*a][j], accf[2*a+1][j]);

#pragma unroll
    for (int a = 0; a < 8; a++) {
        const int co = co0 + cg*8 + a;
        float4 v = make_float4(accf[a][0], accf[a][1], accf[a][2], accf[a][3]);
        *reinterpret_cast<float4*>(
            &outp[(((size_t)n * Cout + co) * HW + y0 + y_l) * HW + x0]) = v;
    }
}

// ---------------------------------------------------------------------------
// Depthwise 3x3 conv (pad 1), one plane per block
// ---------------------------------------------------------------------------
__global__ void dwconv_kernel(const float* __restrict__ in,
                              const float* __restrict__ w,
                              float* __restrict__ outp) {
    if (g_sel[6] == 0.0f) return;
    __shared__ float s[34][34];
    const int plane = blockIdx.x;
    const int c = plane % CCH;
    const float* ip = in + (size_t)plane * PLANE;
    for (int idx = threadIdx.x; idx < 34*34; idx += 256) {
        int r = idx / 34, cc = idx - r*34;
        int yy = r - 1, xx = cc - 1;
        s[r][cc] = (yy >= 0 && yy < 32 && xx >= 0 && xx < 32) ? ip[yy*32 + xx] : 0.f;
    }
    float wv[9];
#pragma unroll
    for (int k = 0; k < 9; k++) wv[k] = w[c*9 + k];
    __syncthreads();
    for (int idx = threadIdx.x; idx < PLANE; idx += 256) {
        int yy = idx >> 5, xx = idx & 31;
        float a = 0.f;
#pragma unroll
        for (int ky = 0; ky < 3; ky++)
#pragma unroll
            for (int kx = 0; kx < 3; kx++)
                a += s[yy+ky][xx+kx] * wv[ky*3+kx];
        outp[(size_t)plane * PLANE + idx] = a;
    }
}

// ---------------------------------------------------------------------------
// 3x3 max pool (pad 1) and 3x3 avg pool (count_include_pad)
// ---------------------------------------------------------------------------
__global__ void maxpool_kernel(const float* __restrict__ in, float* __restrict__ outp) {
    if (g_sel[1] == 0.0f) return;
    __shared__ float s[34][34];
    const int plane = blockIdx.x;
    const float* ip = in + (size_t)plane * PLANE;
    for (int idx = threadIdx.x; idx < 34*34; idx += 256) {
        int r = idx / 34, cc = idx - r*34;
        int yy = r - 1, xx = cc - 1;
        s[r][cc] = (yy >= 0 && yy < 32 && xx >= 0 && xx < 32) ? ip[yy*32 + xx] : -3.0e38f;
    }
    __syncthreads();
    for (int idx = threadIdx.x; idx < PLANE; idx += 256) {
        int yy = idx >> 5, xx = idx & 31;
        float m = -3.0e38f;
#pragma unroll
        for (int ky = 0; ky < 3; ky++)
#pragma unroll
            for (int kx = 0; kx < 3; kx++)
                m = fmaxf(m, s[yy+ky][xx+kx]);
        outp[(size_t)plane * PLANE + idx] = m;
    }
}

__global__ void avgpool_kernel(const float* __restrict__ in, float* __restrict__ outp) {
    if (g_sel[2] == 0.0f) return;
    __shared__ float s[34][34];
    const int plane = blockIdx.x;
    const float* ip = in + (size_t)plane * PLANE;
    for (int idx = threadIdx.x; idx < 34*34; idx += 256) {
        int r = idx / 34, cc = idx - r*34;
        int yy = r - 1, xx = cc - 1;
        s[r][cc] = (yy >= 0 && yy < 32 && xx >= 0 && xx < 32) ? ip[yy*32 + xx] : 0.f;
    }
    __syncthreads();
    const float inv9 = 1.0f / 9.0f;
    for (int idx = threadIdx.x; idx < PLANE; idx += 256) {
        int yy = idx >> 5, xx = idx & 31;
        float a = 0.f;
#pragma unroll
        for (int ky = 0; ky < 3; ky++)
#pragma unroll
            for (int kx = 0; kx < 3; kx++)
                a += s[yy+ky][xx+kx];
        outp[(size_t)plane * PLANE + idx] = a * inv9;
    }
}

// ---------------------------------------------------------------------------
// Per-channel mean/var -> fused BN scale/shift (sel folded in)
// ---------------------------------------------------------------------------
__global__ void stats_kernel(const float* __restrict__ y,
                             const float* __restrict__ g,
                             const float* __restrict__ b,
                             int selIdx) {
    const float sel = (selIdx >= 0) ? g_sel[selIdx] : 1.0f;
    if (sel == 0.0f) return;
    const int c = blockIdx.x;
    const float* base = y + (size_t)c * PLANE;
    float s = 0.f, s2 = 0.f;
    for (int idx = threadIdx.x; idx < NHW; idx += 256) {
        int n = idx >> 10, i = idx & 1023;
        float v = base[(size_t)n * (CCH * PLANE) + i];
        s += v; s2 += v * v;
    }
    __shared__ float rs[256], rs2[256];
    rs[threadIdx.x] = s; rs2[threadIdx.x] = s2;
    __syncthreads();
    for (int o = 128; o > 0; o >>= 1) {
        if (threadIdx.x < o) { rs[threadIdx.x] += rs[threadIdx.x+o]; rs2[threadIdx.x] += rs2[threadIdx.x+o]; }
        __syncthreads();
    }
    if (threadIdx.x == 0) {
        float m   = rs[0] * (1.0f / (float)NHW);
        float var = rs2[0] * (1.0f / (float)NHW) - m * m;
        float inv = rsqrtf(var + 1e-5f);
        float A   = g[c] * inv;
        g_A[c] = sel * A;
        g_B[c] = sel * (b[c] - m * A);
    }
}

// ---------------------------------------------------------------------------
// Elementwise kernels (float4, channel derived from linear index)
// ---------------------------------------------------------------------------
__global__ void norm_relu_kernel(float* __restrict__ h) {
    size_t i4 = (size_t)blockIdx.x * 256 + threadIdx.x;
    int c = (int)((i4 >> 8) & 255);
    float A = g_A[c], Bv = g_B[c];
    float4 v = reinterpret_cast<float4*>(h)[i4];
    v.x = fmaxf(v.x * A + Bv, 0.f);
    v.y = fmaxf(v.y * A + Bv, 0.f);
    v.z = fmaxf(v.z * A + Bv, 0.f);
    v.w = fmaxf(v.w * A + Bv, 0.f);
    reinterpret_cast<float4*>(h)[i4] = v;
}

__global__ void init_out_kernel(float* __restrict__ out, const float* __restrict__ h) {
    size_t i4 = (size_t)blockIdx.x * 256 + threadIdx.x;
    float s = g_sel[3];
    float4 v = reinterpret_cast<const float4*>(h)[i4];
    v.x *= s; v.y *= s; v.z *= s; v.w *= s;
    reinterpret_cast<float4*>(out)[i4] = v;
}

__global__ void accum_kernel(float* __restrict__ out, const float* __restrict__ y, int selIdx) {
    if (g_sel[selIdx] == 0.0f) return;
    size_t i4 = (size_t)blockIdx.x * 256 + threadIdx.x;
    int c = (int)((i4 >> 8) & 255);
    float A = g_A[c], Bv = g_B[c];
    float4 v = reinterpret_cast<const float4*>(y)[i4];
    float4 o = reinterpret_cast<float4*>(out)[i4];
    o.x += v.x * A + Bv;
    o.y += v.y * A + Bv;
    o.z += v.z * A + Bv;
    o.w += v.w * A + Bv;
    reinterpret_cast<float4*>(out)[i4] = o;
}

// ---------------------------------------------------------------------------
// Launch sequence (graph-capturable, allocation-free)
// ---------------------------------------------------------------------------
extern "C" void kernel_launch(void* const* d_in, const int* in_sizes, int n_in,
                              void* d_out, int out_size) {
    const float* x    = (const float*)d_in[0];
    const float* aw   = (const float*)d_in[1];
    const float* w_in = (const float*)d_in[2];
    const float* g_in = (const float*)d_in[3];
    const float* b_in = (const float*)d_in[4];
    const float* w3   = (const float*)d_in[5];
    const float* g3   = (const float*)d_in[6];
    const float* b3   = (const float*)d_in[7];
    const float* w5   = (const float*)d_in[8];
    const float* g5   = (const float*)d_in[9];
    const float* b5   = (const float*)d_in[10];
    const float* w_dw = (const float*)d_in[11];
    const float* w_pw = (const float*)d_in[12];
    const float* gs   = (const float*)d_in[13];
    const float* bs   = (const float*)d_in[14];
    const float* wd   = (const float*)d_in[15];
    const float* gd   = (const float*)d_in[16];
    const float* bd   = (const float*)d_in[17];
    const float* gmp  = (const float*)d_in[18];
    const float* bmp  = (const float*)d_in[19];
    const float* gap  = (const float*)d_in[20];
    const float* bap  = (const float*)d_in[21];
    float* out = (float*)d_out;

    float *h, *y, *t;
    cudaGetSymbolAddress((void**)&h, g_h);
    cudaGetSymbolAddress((void**)&y, g_y);
    cudaGetSymbolAddress((void**)&t, g_t);

    const dim3 convGrid(8, BATCH, CCH / 64);
    const int  eltGrid = NTOT / 4 / 256;   // 16384

    // mixture weights
    sel_kernel<<<1, 32>>>(aw);

    // input transition: conv1x1 -> BN -> ReLU (h)
    conv_kernel<1,1,1,16><<<convGrid, 256>>>(x, w_in, h, CIN_X, CCH, -1);
    stats_kernel<<<CCH, 256>>>(h, g_in, b_in, -1);
    norm_relu_kernel<<<eltGrid, 256>>>(h);

    // out = sel[3] * h (also clears poison)
    init_out_kernel<<<eltGrid, 256>>>(out, h);

    // op 1: max_pool_3x3
    maxpool_kernel<<<NPLANES, 256>>>(h, y);
    stats_kernel<<<CCH, 256>>>(y, gmp, bmp, 1);
    accum_kernel<<<eltGrid, 256>>>(out, y, 1);

    // op 2: avg_pool_3x3
    avgpool_kernel<<<NPLANES, 256>>>(h, y);
    stats_kernel<<<CCH, 256>>>(y, gap, bap, 2);
    accum_kernel<<<eltGrid, 256>>>(out, y, 2);

    // op 4: conv_3x3
    conv_kernel<3,3,1,8><<<convGrid, 256>>>(h, w3, y, CCH, CCH, 4);
    stats_kernel<<<CCH, 256>>>(y, g3, b3, 4);
    accum_kernel<<<eltGrid, 256>>>(out, y, 4);

    // op 5: conv_5x5
    conv_kernel<5,5,1,4><<<convGrid, 256>>>(h, w5, y, CCH, CCH, 5);
    stats_kernel<<<CCH, 256>>>(y, g5, b5, 5);
    accum_kernel<<<eltGrid, 256>>>(out, y, 5);

    // op 6: sep_conv_3x3 (depthwise 3x3 -> pointwise 1x1)
    dwconv_kernel<<<NPLANES, 256>>>(h, w_dw, t);
    conv_kernel<1,1,1,16><<<convGrid, 256>>>(t, w_pw, y, CCH, CCH, 6);
    stats_kernel<<<CCH, 256>>>(y, gs, bs, 6);
    accum_kernel<<<eltGrid, 256>>>(out, y, 6);

    // op 7: dil_conv_3x3 (dilation 2, pad 2)
    conv_kernel<3,3,2,8><<<convGrid, 256>>>(h, wd, y, CCH, CCH, 7);
    stats_kernel<<<CCH, 256>>>(y, gd, bd, 7);
    accum_kernel<<<eltGrid, 256>>>(out, y, 7);
}